// round 2
// baseline (speedup 1.0000x reference)
#include <cuda_runtime.h>
#include <math.h>
#include <float.h>

#define B_    2
#define S_    2048
#define DIM_  2048
#define H_    16
#define KVH_  4
#define HD_   128
#define G_    4
#define M_    (B_*S_)          // 4096 rows total
#define QD_   (H_*HD_)         // 2048
#define KD_   (KVH_*HD_)       // 512

// Scratch (device globals -- no allocation)
__device__ float g_q[(size_t)M_*QD_];     // [b,s,h,hd]
__device__ float g_k[(size_t)M_*KD_];     // [b,s,kvh,hd]
__device__ float g_v[(size_t)M_*KD_];
__device__ float g_attn[(size_t)M_*QD_];  // [b,s,h,hd]

// ---------------------------------------------------------------------------
// GEMM: C[M,N] = A[M,K] * W[N,K]^T   (all fp32, dims divisible by tile sizes)
// 64x64 tile, BK=16, 256 threads, 4x4 per-thread micro-tile.
// ---------------------------------------------------------------------------
__global__ __launch_bounds__(256) void gemm_nt_kernel(
    const float* __restrict__ A, const float* __restrict__ W,
    float* __restrict__ C, int Mn, int Nn, int Kn)
{
    __shared__ float As[16][68];   // [k][m], padded
    __shared__ float Bs[16][68];   // [k][n], padded

    const int tid = threadIdx.x;
    const int ty = tid >> 4;       // 0..15 -> m sub-tile
    const int tx = tid & 15;       // 0..15 -> n sub-tile
    const int m0 = blockIdx.y * 64;
    const int n0 = blockIdx.x * 64;

    const int lr  = tid >> 2;      // 0..63 row within tile for loads
    const int lk4 = (tid & 3) * 4; // 0,4,8,12 k offset for loads

    float acc[4][4];
#pragma unroll
    for (int i = 0; i < 4; ++i)
#pragma unroll
        for (int j = 0; j < 4; ++j) acc[i][j] = 0.f;

    for (int k0 = 0; k0 < Kn; k0 += 16) {
        // load A tile (64x16) transposed into As[k][m]
        float4 av = *(const float4*)&A[(size_t)(m0 + lr) * Kn + k0 + lk4];
        float4 bv = *(const float4*)&W[(size_t)(n0 + lr) * Kn + k0 + lk4];
        As[lk4 + 0][lr] = av.x; As[lk4 + 1][lr] = av.y;
        As[lk4 + 2][lr] = av.z; As[lk4 + 3][lr] = av.w;
        Bs[lk4 + 0][lr] = bv.x; Bs[lk4 + 1][lr] = bv.y;
        Bs[lk4 + 2][lr] = bv.z; Bs[lk4 + 3][lr] = bv.w;
        __syncthreads();

#pragma unroll
        for (int kk = 0; kk < 16; ++kk) {
            float4 a = *(const float4*)&As[kk][ty * 4];
            float4 b = *(const float4*)&Bs[kk][tx * 4];
            acc[0][0] += a.x * b.x; acc[0][1] += a.x * b.y; acc[0][2] += a.x * b.z; acc[0][3] += a.x * b.w;
            acc[1][0] += a.y * b.x; acc[1][1] += a.y * b.y; acc[1][2] += a.y * b.z; acc[1][3] += a.y * b.w;
            acc[2][0] += a.z * b.x; acc[2][1] += a.z * b.y; acc[2][2] += a.z * b.z; acc[2][3] += a.z * b.w;
            acc[3][0] += a.w * b.x; acc[3][1] += a.w * b.y; acc[3][2] += a.w * b.z; acc[3][3] += a.w * b.w;
        }
        __syncthreads();
    }

#pragma unroll
    for (int i = 0; i < 4; ++i) {
        float4 o = make_float4(acc[i][0], acc[i][1], acc[i][2], acc[i][3]);
        *(float4*)&C[(size_t)(m0 + ty * 4 + i) * Nn + n0 + tx * 4] = o;
    }
}

// ---------------------------------------------------------------------------
// RoPE (in place): t layout [b,s,nheads,HD]; freqs [S, HD/2, 2] = (cos,sin)
// ---------------------------------------------------------------------------
__global__ void rope_kernel(float* __restrict__ t, const float* __restrict__ freqs,
                            int nheads)
{
    int i = blockIdx.x * blockDim.x + threadIdx.x;
    int total = B_ * S_ * nheads * (HD_ / 2);
    if (i >= total) return;
    int j = i & 63;                               // HD/2 = 64
    int s = (i / (64 * nheads)) % S_;
    float c  = freqs[((size_t)s * 64 + j) * 2 + 0];
    float sn = freqs[((size_t)s * 64 + j) * 2 + 1];
    float* p = t + (size_t)(i >> 6) * HD_ + 2 * j;
    float x0 = p[0], x1 = p[1];
    p[0] = x0 * c - x1 * sn;
    p[1] = x0 * sn + x1 * c;
}

// ---------------------------------------------------------------------------
// Flash attention (causal, GQA). One block = (b,h) x 64 query rows.
// 256 threads: ty=tid/16 owns rows ty*4..+3; tx=tid%16 owns score cols tx*4..+3
// and output cols tx*8..+7.
// ---------------------------------------------------------------------------
__global__ __launch_bounds__(256) void flash_kernel(
    const float* __restrict__ Q, const float* __restrict__ K,
    const float* __restrict__ V, float* __restrict__ O)
{
    extern __shared__ float sm[];
    float* Qs = sm;                 // [128][64]  (k-major)
    float* Ks = Qs + 128 * 64;      // [128][64]  (k-major)
    float* Vs = Ks + 128 * 64;      // [64][128]  (n,d)
    float* Ps = Vs + 64 * 128;      // [64][64]   (row, n)

    const int bh = blockIdx.x;      // 0..31
    const int ib = blockIdx.y;      // query tile 0..31
    const int b  = bh / H_;
    const int h  = bh % H_;
    const int kv = h / G_;

    const float* Qg = Q + (size_t)b * S_ * QD_ + (size_t)h * HD_;
    const float* Kg = K + (size_t)b * S_ * KD_ + (size_t)kv * HD_;
    const float* Vg = V + (size_t)b * S_ * KD_ + (size_t)kv * HD_;

    const int tid = threadIdx.x;
    const int ty = tid >> 4;
    const int tx = tid & 15;
    const float scale = 0.08838834764831845f;  // 1/sqrt(128)

    // Load persistent Q tile transposed: Qs[d][r]
    for (int i = tid; i < 64 * 32; i += 256) {
        int r = i >> 5, d4 = (i & 31) * 4;
        float4 qv = *(const float4*)&Qg[(size_t)(ib * 64 + r) * QD_ + d4];
        Qs[(d4 + 0) * 64 + r] = qv.x; Qs[(d4 + 1) * 64 + r] = qv.y;
        Qs[(d4 + 2) * 64 + r] = qv.z; Qs[(d4 + 3) * 64 + r] = qv.w;
    }

    float mrow[4], lrow[4], acc[4][8];
#pragma unroll
    for (int i = 0; i < 4; ++i) {
        mrow[i] = -1e30f; lrow[i] = 0.f;
#pragma unroll
        for (int c = 0; c < 8; ++c) acc[i][c] = 0.f;
    }

    for (int j = 0; j <= ib; ++j) {
        __syncthreads();   // previous PV done before overwriting K/V tiles
        // load K tile transposed, V tile natural
        for (int i = tid; i < 64 * 32; i += 256) {
            int n = i >> 5, d4 = (i & 31) * 4;
            float4 kvv = *(const float4*)&Kg[(size_t)(j * 64 + n) * KD_ + d4];
            Ks[(d4 + 0) * 64 + n] = kvv.x; Ks[(d4 + 1) * 64 + n] = kvv.y;
            Ks[(d4 + 2) * 64 + n] = kvv.z; Ks[(d4 + 3) * 64 + n] = kvv.w;
            float4 vv = *(const float4*)&Vg[(size_t)(j * 64 + n) * KD_ + d4];
            *(float4*)&Vs[n * 128 + d4] = vv;
        }
        __syncthreads();

        // scores: s[4][4] = Q(4 rows) . K(4 cols)
        float s[4][4];
#pragma unroll
        for (int i = 0; i < 4; ++i)
#pragma unroll
            for (int jj = 0; jj < 4; ++jj) s[i][jj] = 0.f;

#pragma unroll 4
        for (int k = 0; k < 128; ++k) {
            float4 a = *(const float4*)&Qs[k * 64 + ty * 4];
            float4 kb = *(const float4*)&Ks[k * 64 + tx * 4];
            s[0][0] += a.x * kb.x; s[0][1] += a.x * kb.y; s[0][2] += a.x * kb.z; s[0][3] += a.x * kb.w;
            s[1][0] += a.y * kb.x; s[1][1] += a.y * kb.y; s[1][2] += a.y * kb.z; s[1][3] += a.y * kb.w;
            s[2][0] += a.z * kb.x; s[2][1] += a.z * kb.y; s[2][2] += a.z * kb.z; s[2][3] += a.z * kb.w;
            s[3][0] += a.w * kb.x; s[3][1] += a.w * kb.y; s[3][2] += a.w * kb.z; s[3][3] += a.w * kb.w;
        }

        const bool diag = (j == ib);
#pragma unroll
        for (int ii = 0; ii < 4; ++ii) {
            int qr = ib * 64 + ty * 4 + ii;
            float vmax = -1e30f;
#pragma unroll
            for (int jj = 0; jj < 4; ++jj) {
                float val = s[ii][jj] * scale;
                if (diag && (j * 64 + tx * 4 + jj > qr)) val = -1e30f;
                s[ii][jj] = val;
                vmax = fmaxf(vmax, val);
            }
            // row-max across the 16 tx lanes (they are 16 consecutive lanes)
#pragma unroll
            for (int o = 1; o < 16; o <<= 1)
                vmax = fmaxf(vmax, __shfl_xor_sync(0xffffffffu, vmax, o));
            float mnew = fmaxf(mrow[ii], vmax);
            float alpha = __expf(mrow[ii] - mnew);
            float p0 = __expf(s[ii][0] - mnew);
            float p1 = __expf(s[ii][1] - mnew);
            float p2 = __expf(s[ii][2] - mnew);
            float p3 = __expf(s[ii][3] - mnew);
            float psum = p0 + p1 + p2 + p3;
#pragma unroll
            for (int o = 1; o < 16; o <<= 1)
                psum += __shfl_xor_sync(0xffffffffu, psum, o);
            lrow[ii] = lrow[ii] * alpha + psum;
            mrow[ii] = mnew;
#pragma unroll
            for (int c = 0; c < 8; ++c) acc[ii][c] *= alpha;
            *(float4*)&Ps[(ty * 4 + ii) * 64 + tx * 4] = make_float4(p0, p1, p2, p3);
        }
        __syncthreads();

        // PV: acc[4][8] += P[rows][n] * V[n][tx*8..+7]
#pragma unroll 2
        for (int n = 0; n < 64; ++n) {
            float4 v0 = *(const float4*)&Vs[n * 128 + tx * 8];
            float4 v1 = *(const float4*)&Vs[n * 128 + tx * 8 + 4];
#pragma unroll
            for (int ii = 0; ii < 4; ++ii) {
                float p = Ps[(ty * 4 + ii) * 64 + n];
                acc[ii][0] += p * v0.x; acc[ii][1] += p * v0.y;
                acc[ii][2] += p * v0.z; acc[ii][3] += p * v0.w;
                acc[ii][4] += p * v1.x; acc[ii][5] += p * v1.y;
                acc[ii][6] += p * v1.z; acc[ii][7] += p * v1.w;
            }
        }
    }

    // epilogue: normalize and write [b,s,h,hd]
#pragma unroll
    for (int ii = 0; ii < 4; ++ii) {
        float inv = 1.f / lrow[ii];
        int row = ib * 64 + ty * 4 + ii;
        float* dst = O + (size_t)(b * S_ + row) * QD_ + (size_t)h * HD_ + tx * 8;
        float4 o0 = make_float4(acc[ii][0] * inv, acc[ii][1] * inv, acc[ii][2] * inv, acc[ii][3] * inv);
        float4 o1 = make_float4(acc[ii][4] * inv, acc[ii][5] * inv, acc[ii][6] * inv, acc[ii][7] * inv);
        *(float4*)&dst[0] = o0;
        *(float4*)&dst[4] = o1;
    }
}

// ---------------------------------------------------------------------------
extern "C" void kernel_launch(void* const* d_in, const int* in_sizes, int n_in,
                              void* d_out, int out_size)
{
    const float* x     = (const float*)d_in[0];
    const float* freqs = (const float*)d_in[1];
    const float* wq    = (const float*)d_in[2];
    const float* wk    = (const float*)d_in[3];
    const float* wv    = (const float*)d_in[4];
    const float* wo    = (const float*)d_in[5];
    float* out = (float*)d_out;

    float *q, *k, *v, *attn;
    cudaGetSymbolAddress((void**)&q,    g_q);
    cudaGetSymbolAddress((void**)&k,    g_k);
    cudaGetSymbolAddress((void**)&v,    g_v);
    cudaGetSymbolAddress((void**)&attn, g_attn);

    // QKV projections
    gemm_nt_kernel<<<dim3(QD_ / 64, M_ / 64), 256>>>(x, wq, q, M_, QD_, DIM_);
    gemm_nt_kernel<<<dim3(KD_ / 64, M_ / 64), 256>>>(x, wk, k, M_, KD_, DIM_);
    gemm_nt_kernel<<<dim3(KD_ / 64, M_ / 64), 256>>>(x, wv, v, M_, KD_, DIM_);

    // RoPE
    {
        int tq = B_ * S_ * H_ * (HD_ / 2);
        int tk = B_ * S_ * KVH_ * (HD_ / 2);
        rope_kernel<<<(tq + 255) / 256, 256>>>(q, freqs, H_);
        rope_kernel<<<(tk + 255) / 256, 256>>>(k, freqs, KVH_);
    }

    // Flash attention
    {
        static int smem_set = 0;
        const int smem_bytes = (128 * 64 + 128 * 64 + 64 * 128 + 64 * 64) * 4; // 114688
        if (!smem_set) {
            cudaFuncSetAttribute(flash_kernel,
                                 cudaFuncAttributeMaxDynamicSharedMemorySize, smem_bytes);
            smem_set = 1;
        }
        flash_kernel<<<dim3(B_ * H_, S_ / 64), 256, smem_bytes>>>(q, k, v, attn);
    }

    // Output projection
    gemm_nt_kernel<<<dim3(DIM_ / 64, M_ / 64), 256>>>(attn, wo, out, M_, DIM_, QD_);
}

// round 4
// speedup vs baseline: 1.2858x; 1.2858x over previous
#include <cuda_runtime.h>
#include <math.h>
#include <float.h>

#define B_    2
#define S_    2048
#define DIM_  2048
#define H_    16
#define KVH_  4
#define HD_   128
#define G_    4
#define M_    (B_*S_)          // 4096 rows total
#define QD_   (H_*HD_)         // 2048
#define KD_   (KVH_*HD_)       // 512

// Scratch (device globals -- no allocation)
__device__ float g_q[(size_t)M_*QD_];     // [b,s,h,hd]
__device__ float g_k[(size_t)M_*KD_];     // [b,s,kvh,hd]
__device__ float g_v[(size_t)M_*KD_];
__device__ float g_attn[(size_t)M_*QD_];  // [b,s,h,hd]

// ---------------------------------------------------------------------------
// 3xTF32 tensor-core GEMM: C[M,N] = A[M,K] * W[N,K]^T  (fp32-accurate)
// 128x128x32 block tile, 256 threads (8 warps, 2x4), warp tile 64x32.
// cp.async double-buffered smem, XOR-swizzled for conflict-free frag loads.
// Each fp32 operand split hi/lo into tf32; D += Ahi*Bhi + Ahi*Blo + Alo*Bhi.
// ---------------------------------------------------------------------------
__device__ __forceinline__ void cp_async16(unsigned saddr, const void* gptr) {
    asm volatile("cp.async.cg.shared.global [%0], [%1], 16;" :: "r"(saddr), "l"(gptr));
}

__device__ __forceinline__ unsigned f2tf32(float x) {
    unsigned r;
    asm("cvt.rna.tf32.f32 %0, %1;" : "=r"(r) : "f"(x));
    return r;
}

#define MMA_TF32(d, a0, a1, a2, a3, b0, b1) \
    asm volatile("mma.sync.aligned.m16n8k8.row.col.f32.tf32.tf32.f32 " \
                 "{%0,%1,%2,%3},{%4,%5,%6,%7},{%8,%9},{%0,%1,%2,%3};" \
                 : "+f"(d[0]), "+f"(d[1]), "+f"(d[2]), "+f"(d[3]) \
                 : "r"(a0), "r"(a1), "r"(a2), "r"(a3), "r"(b0), "r"(b1))

__global__ __launch_bounds__(256, 2) void gemm_tf32x3_kernel(
    const float* __restrict__ A, const float* __restrict__ W,
    float* __restrict__ C, int Nn, int Kn)
{
    extern __shared__ float smem[];   // 2 stages * (A 4096 + B 4096) floats = 64KB
    unsigned smb = (unsigned)__cvta_generic_to_shared(smem);

    const int tid  = threadIdx.x;
    const int lane = tid & 31;
    const int warp = tid >> 5;
    const int warpM = (warp >> 2) * 64;   // 0 or 64
    const int warpN = (warp & 3) * 32;    // 0,32,64,96
    const int r = lane >> 2;              // 0..7
    const int c = lane & 3;               // 0..3
    const int m0 = blockIdx.y * 128;
    const int n0 = blockIdx.x * 128;

    const int lrow = tid >> 3;            // 0..31
    const int lg   = tid & 7;             // float4 group 0..7

    float acc[4][4][4];
#pragma unroll
    for (int i = 0; i < 4; ++i)
#pragma unroll
        for (int j = 0; j < 4; ++j)
#pragma unroll
            for (int t = 0; t < 4; ++t) acc[i][j][t] = 0.f;

    const int NT = Kn >> 5;  // 32-wide k tiles

    auto load_tile = [&](int it, int p) {
        size_t k0 = (size_t)it * 32 + lg * 4;
#pragma unroll
        for (int i = 0; i < 4; ++i) {
            int rr = lrow + i * 32;
            int sw = ((lg ^ (rr & 7)) << 2);
            unsigned sa = smb + (unsigned)(p * 8192 + rr * 32 + sw) * 4u;
            cp_async16(sa, &A[(size_t)(m0 + rr) * Kn + k0]);
            unsigned sb = smb + (unsigned)(p * 8192 + 4096 + rr * 32 + sw) * 4u;
            cp_async16(sb, &W[(size_t)(n0 + rr) * Kn + k0]);
        }
        asm volatile("cp.async.commit_group;" ::: "memory");
    };

    load_tile(0, 0);

    for (int it = 0; it < NT; ++it) {
        if (it + 1 < NT) {
            load_tile(it + 1, (it + 1) & 1);
            asm volatile("cp.async.wait_group 1;" ::: "memory");
        } else {
            asm volatile("cp.async.wait_group 0;" ::: "memory");
        }
        __syncthreads();

        const float* As = smem + (it & 1) * 8192;
        const float* Bs = As + 4096;

#pragma unroll
        for (int kk = 0; kk < 4; ++kk) {
            const int off0 = (((2 * kk) ^ r) << 2) + c;
            const int off1 = (((2 * kk + 1) ^ r) << 2) + c;

            // B fragments: hi/lo split
            unsigned bh[4][2], bl[4][2];
#pragma unroll
            for (int bn = 0; bn < 4; ++bn) {
                int n1 = warpN + bn * 8 + r;
                float v0 = Bs[n1 * 32 + off0];
                float v1 = Bs[n1 * 32 + off1];
                bh[bn][0] = f2tf32(v0);
                bh[bn][1] = f2tf32(v1);
                bl[bn][0] = f2tf32(v0 - __uint_as_float(bh[bn][0]));
                bl[bn][1] = f2tf32(v1 - __uint_as_float(bh[bn][1]));
            }

#pragma unroll
            for (int am = 0; am < 4; ++am) {
                int m1 = warpM + am * 16 + r;
                float a0 = As[m1 * 32 + off0];
                float a1 = As[(m1 + 8) * 32 + off0];
                float a2 = As[m1 * 32 + off1];
                float a3 = As[(m1 + 8) * 32 + off1];
                unsigned ah0 = f2tf32(a0), ah1 = f2tf32(a1);
                unsigned ah2 = f2tf32(a2), ah3 = f2tf32(a3);
                unsigned al0 = f2tf32(a0 - __uint_as_float(ah0));
                unsigned al1 = f2tf32(a1 - __uint_as_float(ah1));
                unsigned al2 = f2tf32(a2 - __uint_as_float(ah2));
                unsigned al3 = f2tf32(a3 - __uint_as_float(ah3));
#pragma unroll
                for (int bn = 0; bn < 4; ++bn) {
                    MMA_TF32(acc[am][bn], ah0, ah1, ah2, ah3, bh[bn][0], bh[bn][1]);
                    MMA_TF32(acc[am][bn], ah0, ah1, ah2, ah3, bl[bn][0], bl[bn][1]);
                    MMA_TF32(acc[am][bn], al0, al1, al2, al3, bh[bn][0], bh[bn][1]);
                }
            }
        }
        __syncthreads();
    }

    // epilogue
#pragma unroll
    for (int am = 0; am < 4; ++am) {
        int m1 = m0 + warpM + am * 16 + r;
#pragma unroll
        for (int bn = 0; bn < 4; ++bn) {
            int n1 = n0 + warpN + bn * 8 + 2 * c;
            *(float2*)&C[(size_t)m1 * Nn + n1] = make_float2(acc[am][bn][0], acc[am][bn][1]);
            *(float2*)&C[(size_t)(m1 + 8) * Nn + n1] = make_float2(acc[am][bn][2], acc[am][bn][3]);
        }
    }
}

// ---------------------------------------------------------------------------
// RoPE (in place): t layout [b,s,nheads,HD]; freqs [S, HD/2, 2] = (cos,sin)
// ---------------------------------------------------------------------------
__global__ void rope_kernel(float* __restrict__ t, const float* __restrict__ freqs,
                            int nheads)
{
    int i = blockIdx.x * blockDim.x + threadIdx.x;
    int total = B_ * S_ * nheads * (HD_ / 2);
    if (i >= total) return;
    int j = i & 63;                               // HD/2 = 64
    int s = (i / (64 * nheads)) % S_;
    float c  = freqs[((size_t)s * 64 + j) * 2 + 0];
    float sn = freqs[((size_t)s * 64 + j) * 2 + 1];
    float* p = t + (size_t)(i >> 6) * HD_ + 2 * j;
    float x0 = p[0], x1 = p[1];
    p[0] = x0 * c - x1 * sn;
    p[1] = x0 * sn + x1 * c;
}

// ---------------------------------------------------------------------------
// Flash attention (causal, GQA). One block = (b,h) x 64 query rows. fp32.
// ---------------------------------------------------------------------------
__global__ __launch_bounds__(256) void flash_kernel(
    const float* __restrict__ Q, const float* __restrict__ K,
    const float* __restrict__ V, float* __restrict__ O)
{
    extern __shared__ float sm[];
    float* Qs = sm;                 // [128][64]  (k-major)
    float* Ks = Qs + 128 * 64;      // [128][64]  (k-major)
    float* Vs = Ks + 128 * 64;      // [64][128]  (n,d)
    float* Ps = Vs + 64 * 128;      // [64][64]   (row, n)

    const int bh = blockIdx.x;      // 0..31
    const int ib = blockIdx.y;      // query tile 0..31
    const int b  = bh / H_;
    const int h  = bh % H_;
    const int kv = h / G_;

    const float* Qg = Q + (size_t)b * S_ * QD_ + (size_t)h * HD_;
    const float* Kg = K + (size_t)b * S_ * KD_ + (size_t)kv * HD_;
    const float* Vg = V + (size_t)b * S_ * KD_ + (size_t)kv * HD_;

    const int tid = threadIdx.x;
    const int ty = tid >> 4;
    const int tx = tid & 15;
    const float scale = 0.08838834764831845f;  // 1/sqrt(128)

    // Load persistent Q tile transposed: Qs[d][r]
    for (int i = tid; i < 64 * 32; i += 256) {
        int r = i >> 5, d4 = (i & 31) * 4;
        float4 qv = *(const float4*)&Qg[(size_t)(ib * 64 + r) * QD_ + d4];
        Qs[(d4 + 0) * 64 + r] = qv.x; Qs[(d4 + 1) * 64 + r] = qv.y;
        Qs[(d4 + 2) * 64 + r] = qv.z; Qs[(d4 + 3) * 64 + r] = qv.w;
    }

    float mrow[4], lrow[4], acc[4][8];
#pragma unroll
    for (int i = 0; i < 4; ++i) {
        mrow[i] = -1e30f; lrow[i] = 0.f;
#pragma unroll
        for (int c = 0; c < 8; ++c) acc[i][c] = 0.f;
    }

    for (int j = 0; j <= ib; ++j) {
        __syncthreads();   // previous PV done before overwriting K/V tiles
        // load K tile transposed, V tile natural
        for (int i = tid; i < 64 * 32; i += 256) {
            int n = i >> 5, d4 = (i & 31) * 4;
            float4 kvv = *(const float4*)&Kg[(size_t)(j * 64 + n) * KD_ + d4];
            Ks[(d4 + 0) * 64 + n] = kvv.x; Ks[(d4 + 1) * 64 + n] = kvv.y;
            Ks[(d4 + 2) * 64 + n] = kvv.z; Ks[(d4 + 3) * 64 + n] = kvv.w;
            float4 vv = *(const float4*)&Vg[(size_t)(j * 64 + n) * KD_ + d4];
            *(float4*)&Vs[n * 128 + d4] = vv;
        }
        __syncthreads();

        // scores: s[4][4] = Q(4 rows) . K(4 cols)
        float s[4][4];
#pragma unroll
        for (int i = 0; i < 4; ++i)
#pragma unroll
            for (int jj = 0; jj < 4; ++jj) s[i][jj] = 0.f;

#pragma unroll 4
        for (int k = 0; k < 128; ++k) {
            float4 a = *(const float4*)&Qs[k * 64 + ty * 4];
            float4 kb = *(const float4*)&Ks[k * 64 + tx * 4];
            s[0][0] += a.x * kb.x; s[0][1] += a.x * kb.y; s[0][2] += a.x * kb.z; s[0][3] += a.x * kb.w;
            s[1][0] += a.y * kb.x; s[1][1] += a.y * kb.y; s[1][2] += a.y * kb.z; s[1][3] += a.y * kb.w;
            s[2][0] += a.z * kb.x; s[2][1] += a.z * kb.y; s[2][2] += a.z * kb.z; s[2][3] += a.z * kb.w;
            s[3][0] += a.w * kb.x; s[3][1] += a.w * kb.y; s[3][2] += a.w * kb.z; s[3][3] += a.w * kb.w;
        }

        const bool diag = (j == ib);
#pragma unroll
        for (int ii = 0; ii < 4; ++ii) {
            int qr = ib * 64 + ty * 4 + ii;
            float vmax = -1e30f;
#pragma unroll
            for (int jj = 0; jj < 4; ++jj) {
                float val = s[ii][jj] * scale;
                if (diag && (j * 64 + tx * 4 + jj > qr)) val = -1e30f;
                s[ii][jj] = val;
                vmax = fmaxf(vmax, val);
            }
#pragma unroll
            for (int o = 1; o < 16; o <<= 1)
                vmax = fmaxf(vmax, __shfl_xor_sync(0xffffffffu, vmax, o));
            float mnew = fmaxf(mrow[ii], vmax);
            float alpha = __expf(mrow[ii] - mnew);
            float p0 = __expf(s[ii][0] - mnew);
            float p1 = __expf(s[ii][1] - mnew);
            float p2 = __expf(s[ii][2] - mnew);
            float p3 = __expf(s[ii][3] - mnew);
            float psum = p0 + p1 + p2 + p3;
#pragma unroll
            for (int o = 1; o < 16; o <<= 1)
                psum += __shfl_xor_sync(0xffffffffu, psum, o);
            lrow[ii] = lrow[ii] * alpha + psum;
            mrow[ii] = mnew;
#pragma unroll
            for (int c = 0; c < 8; ++c) acc[ii][c] *= alpha;
            *(float4*)&Ps[(ty * 4 + ii) * 64 + tx * 4] = make_float4(p0, p1, p2, p3);
        }
        __syncthreads();

        // PV: acc[4][8] += P[rows][n] * V[n][tx*8..+7]
#pragma unroll 2
        for (int n = 0; n < 64; ++n) {
            float4 v0 = *(const float4*)&Vs[n * 128 + tx * 8];
            float4 v1 = *(const float4*)&Vs[n * 128 + tx * 8 + 4];
#pragma unroll
            for (int ii = 0; ii < 4; ++ii) {
                float p = Ps[(ty * 4 + ii) * 64 + n];
                acc[ii][0] += p * v0.x; acc[ii][1] += p * v0.y;
                acc[ii][2] += p * v0.z; acc[ii][3] += p * v0.w;
                acc[ii][4] += p * v1.x; acc[ii][5] += p * v1.y;
                acc[ii][6] += p * v1.z; acc[ii][7] += p * v1.w;
            }
        }
    }

    // epilogue: normalize and write [b,s,h,hd]
#pragma unroll
    for (int ii = 0; ii < 4; ++ii) {
        float inv = 1.f / lrow[ii];
        int row = ib * 64 + ty * 4 + ii;
        float* dst = O + (size_t)(b * S_ + row) * QD_ + (size_t)h * HD_ + tx * 8;
        float4 o0 = make_float4(acc[ii][0] * inv, acc[ii][1] * inv, acc[ii][2] * inv, acc[ii][3] * inv);
        float4 o1 = make_float4(acc[ii][4] * inv, acc[ii][5] * inv, acc[ii][6] * inv, acc[ii][7] * inv);
        *(float4*)&dst[0] = o0;
        *(float4*)&dst[4] = o1;
    }
}

// ---------------------------------------------------------------------------
extern "C" void kernel_launch(void* const* d_in, const int* in_sizes, int n_in,
                              void* d_out, int out_size)
{
    const float* x     = (const float*)d_in[0];
    const float* freqs = (const float*)d_in[1];
    const float* wq    = (const float*)d_in[2];
    const float* wk    = (const float*)d_in[3];
    const float* wv    = (const float*)d_in[4];
    const float* wo    = (const float*)d_in[5];
    float* out = (float*)d_out;

    float *q, *k, *v, *attn;
    cudaGetSymbolAddress((void**)&q,    g_q);
    cudaGetSymbolAddress((void**)&k,    g_k);
    cudaGetSymbolAddress((void**)&v,    g_v);
    cudaGetSymbolAddress((void**)&attn, g_attn);

    static int attr_set = 0;
    const int gemm_smem = 65536;
    const int flash_smem = (128 * 64 + 128 * 64 + 64 * 128 + 64 * 64) * 4; // 114688
    if (!attr_set) {
        cudaFuncSetAttribute(gemm_tf32x3_kernel,
                             cudaFuncAttributeMaxDynamicSharedMemorySize, gemm_smem);
        cudaFuncSetAttribute(flash_kernel,
                             cudaFuncAttributeMaxDynamicSharedMemorySize, flash_smem);
        attr_set = 1;
    }

    // QKV projections (3xtf32 tensor-core)
    gemm_tf32x3_kernel<<<dim3(QD_ / 128, M_ / 128), 256, gemm_smem>>>(x, wq, q, QD_, DIM_);
    gemm_tf32x3_kernel<<<dim3(KD_ / 128, M_ / 128), 256, gemm_smem>>>(x, wk, k, KD_, DIM_);
    gemm_tf32x3_kernel<<<dim3(KD_ / 128, M_ / 128), 256, gemm_smem>>>(x, wv, v, KD_, DIM_);

    // RoPE
    {
        int tq = B_ * S_ * H_ * (HD_ / 2);
        int tk = B_ * S_ * KVH_ * (HD_ / 2);
        rope_kernel<<<(tq + 255) / 256, 256>>>(q, freqs, H_);
        rope_kernel<<<(tk + 255) / 256, 256>>>(k, freqs, KVH_);
    }

    // Flash attention (fp32)
    flash_kernel<<<dim3(B_ * H_, S_ / 64), 256, flash_smem>>>(q, k, v, attn);

    // Output projection (3xtf32 tensor-core)
    gemm_tf32x3_kernel<<<dim3(DIM_ / 128, M_ / 128), 256, gemm_smem>>>(attn, wo, out, DIM_, QD_);
}

// round 5
// speedup vs baseline: 2.2670x; 1.7631x over previous
#include <cuda_runtime.h>
#include <math.h>
#include <float.h>

#define B_    2
#define S_    2048
#define DIM_  2048
#define H_    16
#define KVH_  4
#define HD_   128
#define G_    4
#define M_    (B_*S_)          // 4096 rows total
#define QD_   (H_*HD_)         // 2048
#define KD_   (KVH_*HD_)       // 512

// Scratch (device globals -- no allocation)
__device__ float g_q[(size_t)M_*QD_];     // [b,s,h,hd]
__device__ float g_k[(size_t)M_*KD_];     // [b,s,kvh,hd]
__device__ float g_v[(size_t)M_*KD_];
__device__ float g_attn[(size_t)M_*QD_];  // [b,s,h,hd]

// ---------------------------------------------------------------------------
// helpers
// ---------------------------------------------------------------------------
__device__ __forceinline__ void cp_async16(unsigned saddr, const void* gptr) {
    asm volatile("cp.async.cg.shared.global [%0], [%1], 16;" :: "r"(saddr), "l"(gptr));
}

__device__ __forceinline__ unsigned f2tf32(float x) {
    unsigned r;
    asm("cvt.rna.tf32.f32 %0, %1;" : "=r"(r) : "f"(x));
    return r;
}

// pack two floats into bf16x2: low half = lo_elem, high half = hi_elem
__device__ __forceinline__ unsigned pk2(float lo_elem, float hi_elem) {
    unsigned d;
    asm("cvt.rn.bf16x2.f32 %0, %1, %2;" : "=r"(d) : "f"(hi_elem), "f"(lo_elem));
    return d;
}
__device__ __forceinline__ float blo(unsigned u) { return __uint_as_float(u << 16); }
__device__ __forceinline__ float bhi(unsigned u) { return __uint_as_float(u & 0xffff0000u); }

#define MMA_TF32(d, a0, a1, a2, a3, b0, b1) \
    asm volatile("mma.sync.aligned.m16n8k8.row.col.f32.tf32.tf32.f32 " \
                 "{%0,%1,%2,%3},{%4,%5,%6,%7},{%8,%9},{%0,%1,%2,%3};" \
                 : "+f"(d[0]), "+f"(d[1]), "+f"(d[2]), "+f"(d[3]) \
                 : "r"(a0), "r"(a1), "r"(a2), "r"(a3), "r"(b0), "r"(b1))

#define MMA_BF16(d, a0, a1, a2, a3, b0, b1) \
    asm volatile("mma.sync.aligned.m16n8k16.row.col.f32.bf16.bf16.f32 " \
                 "{%0,%1,%2,%3},{%4,%5,%6,%7},{%8,%9},{%0,%1,%2,%3};" \
                 : "+f"(d[0]), "+f"(d[1]), "+f"(d[2]), "+f"(d[3]) \
                 : "r"(a0), "r"(a1), "r"(a2), "r"(a3), "r"(b0), "r"(b1))

// ---------------------------------------------------------------------------
// 3xTF32 tensor-core GEMM: C[M,N] = A[M,K] * W[N,K]^T  (fp32-accurate)
// ---------------------------------------------------------------------------
__global__ __launch_bounds__(256, 2) void gemm_tf32x3_kernel(
    const float* __restrict__ A, const float* __restrict__ W,
    float* __restrict__ C, int Nn, int Kn)
{
    extern __shared__ float smem[];   // 2 stages * (A 4096 + B 4096) floats = 64KB
    unsigned smb = (unsigned)__cvta_generic_to_shared(smem);

    const int tid  = threadIdx.x;
    const int lane = tid & 31;
    const int warp = tid >> 5;
    const int warpM = (warp >> 2) * 64;
    const int warpN = (warp & 3) * 32;
    const int r = lane >> 2;
    const int c = lane & 3;
    const int m0 = blockIdx.y * 128;
    const int n0 = blockIdx.x * 128;

    const int lrow = tid >> 3;
    const int lg   = tid & 7;

    float acc[4][4][4];
#pragma unroll
    for (int i = 0; i < 4; ++i)
#pragma unroll
        for (int j = 0; j < 4; ++j)
#pragma unroll
            for (int t = 0; t < 4; ++t) acc[i][j][t] = 0.f;

    const int NT = Kn >> 5;

    auto load_tile = [&](int it, int p) {
        size_t k0 = (size_t)it * 32 + lg * 4;
#pragma unroll
        for (int i = 0; i < 4; ++i) {
            int rr = lrow + i * 32;
            int sw = ((lg ^ (rr & 7)) << 2);
            unsigned sa = smb + (unsigned)(p * 8192 + rr * 32 + sw) * 4u;
            cp_async16(sa, &A[(size_t)(m0 + rr) * Kn + k0]);
            unsigned sb = smb + (unsigned)(p * 8192 + 4096 + rr * 32 + sw) * 4u;
            cp_async16(sb, &W[(size_t)(n0 + rr) * Kn + k0]);
        }
        asm volatile("cp.async.commit_group;" ::: "memory");
    };

    load_tile(0, 0);

    for (int it = 0; it < NT; ++it) {
        if (it + 1 < NT) {
            load_tile(it + 1, (it + 1) & 1);
            asm volatile("cp.async.wait_group 1;" ::: "memory");
        } else {
            asm volatile("cp.async.wait_group 0;" ::: "memory");
        }
        __syncthreads();

        const float* As = smem + (it & 1) * 8192;
        const float* Bs = As + 4096;

#pragma unroll
        for (int kk = 0; kk < 4; ++kk) {
            const int off0 = (((2 * kk) ^ r) << 2) + c;
            const int off1 = (((2 * kk + 1) ^ r) << 2) + c;

            unsigned bh_[4][2], bl_[4][2];
#pragma unroll
            for (int bn = 0; bn < 4; ++bn) {
                int n1 = warpN + bn * 8 + r;
                float v0 = Bs[n1 * 32 + off0];
                float v1 = Bs[n1 * 32 + off1];
                bh_[bn][0] = f2tf32(v0);
                bh_[bn][1] = f2tf32(v1);
                bl_[bn][0] = f2tf32(v0 - __uint_as_float(bh_[bn][0]));
                bl_[bn][1] = f2tf32(v1 - __uint_as_float(bh_[bn][1]));
            }

#pragma unroll
            for (int am = 0; am < 4; ++am) {
                int m1 = warpM + am * 16 + r;
                float a0 = As[m1 * 32 + off0];
                float a1 = As[(m1 + 8) * 32 + off0];
                float a2 = As[m1 * 32 + off1];
                float a3 = As[(m1 + 8) * 32 + off1];
                unsigned ah0 = f2tf32(a0), ah1 = f2tf32(a1);
                unsigned ah2 = f2tf32(a2), ah3 = f2tf32(a3);
                unsigned al0 = f2tf32(a0 - __uint_as_float(ah0));
                unsigned al1 = f2tf32(a1 - __uint_as_float(ah1));
                unsigned al2 = f2tf32(a2 - __uint_as_float(ah2));
                unsigned al3 = f2tf32(a3 - __uint_as_float(ah3));
#pragma unroll
                for (int bn = 0; bn < 4; ++bn) {
                    MMA_TF32(acc[am][bn], ah0, ah1, ah2, ah3, bh_[bn][0], bh_[bn][1]);
                    MMA_TF32(acc[am][bn], ah0, ah1, ah2, ah3, bl_[bn][0], bl_[bn][1]);
                    MMA_TF32(acc[am][bn], al0, al1, al2, al3, bh_[bn][0], bh_[bn][1]);
                }
            }
        }
        __syncthreads();
    }

#pragma unroll
    for (int am = 0; am < 4; ++am) {
        int m1 = m0 + warpM + am * 16 + r;
#pragma unroll
        for (int bn = 0; bn < 4; ++bn) {
            int n1 = n0 + warpN + bn * 8 + 2 * c;
            *(float2*)&C[(size_t)m1 * Nn + n1] = make_float2(acc[am][bn][0], acc[am][bn][1]);
            *(float2*)&C[(size_t)(m1 + 8) * Nn + n1] = make_float2(acc[am][bn][2], acc[am][bn][3]);
        }
    }
}

// ---------------------------------------------------------------------------
// RoPE (in place)
// ---------------------------------------------------------------------------
__global__ void rope_kernel(float* __restrict__ t, const float* __restrict__ freqs,
                            int nheads)
{
    int i = blockIdx.x * blockDim.x + threadIdx.x;
    int total = B_ * S_ * nheads * (HD_ / 2);
    if (i >= total) return;
    int j = i & 63;
    int s = (i / (64 * nheads)) % S_;
    float c  = freqs[((size_t)s * 64 + j) * 2 + 0];
    float sn = freqs[((size_t)s * 64 + j) * 2 + 1];
    float* p = t + (size_t)(i >> 6) * HD_ + 2 * j;
    float x0 = p[0], x1 = p[1];
    p[0] = x0 * c - x1 * sn;
    p[1] = x0 * sn + x1 * c;
}

// ---------------------------------------------------------------------------
// Flash attention, bf16x3 tensor-core version (causal, GQA).
// Block: 256 thr (8 warps). q-tile 128 rows, kv-tile 64. Warp w owns q rows
// [w*16, w*16+16). Q/K/V split hi/lo bf16 in smem; P kept in registers.
//
// smem word (u32=bf16x2) layout, row stride 68 words (64 data pairs + 4 pad):
//   QHI[128][68], QLO[128][68], KHI[64][68], KLO[64][68], VHI[64][68], VLO[64][68]
// ---------------------------------------------------------------------------
#define QHI_OFF 0
#define QLO_OFF 8704
#define KHI_OFF 17408
#define KLO_OFF 21760
#define VHI_OFF 26112
#define VLO_OFF 30464
#define FLASH_SMEM_WORDS 34816

__global__ __launch_bounds__(256, 1) void flash_bf16_kernel(
    const float* __restrict__ Q, const float* __restrict__ K,
    const float* __restrict__ V, float* __restrict__ O)
{
    extern __shared__ unsigned smw[];
    unsigned* QHI = smw + QHI_OFF;
    unsigned* QLO = smw + QLO_OFF;
    unsigned* KHI = smw + KHI_OFF;
    unsigned* KLO = smw + KLO_OFF;
    unsigned* VHI = smw + VHI_OFF;
    unsigned* VLO = smw + VLO_OFF;
    const unsigned smb = (unsigned)__cvta_generic_to_shared(smw);

    const int bh = blockIdx.x;                 // 0..31
    const int ib = (int)gridDim.y - 1 - (int)blockIdx.y;  // heavy tiles first
    const int b  = bh / H_;
    const int h  = bh % H_;
    const int kv = h / G_;

    const float* Qg = Q + (size_t)b * S_ * QD_ + (size_t)h * HD_;
    const float* Kg = K + (size_t)b * S_ * KD_ + (size_t)kv * HD_;
    const float* Vg = V + (size_t)b * S_ * KD_ + (size_t)kv * HD_;

    const int tid  = threadIdx.x;
    const int lane = tid & 31;
    const int warp = tid >> 5;
    const int r = lane >> 2;      // 0..7
    const int c = lane & 3;       // 0..3
    const float scale = 0.08838834764831845f;

    // ---- load + convert Q tile (128 x 128) once ----
    for (int i = tid; i < 128 * 32; i += 256) {
        int row = i >> 5;
        int hd4 = (i & 31) * 4;
        float4 f = *(const float4*)&Qg[(size_t)(ib * 128 + row) * QD_ + hd4];
        unsigned h0 = pk2(f.x, f.y), h1 = pk2(f.z, f.w);
        unsigned l0 = pk2(f.x - blo(h0), f.y - bhi(h0));
        unsigned l1 = pk2(f.z - blo(h1), f.w - bhi(h1));
        int w = row * 68 + (hd4 >> 1);
        QHI[w] = h0; QHI[w + 1] = h1;
        QLO[w] = l0; QLO[w + 1] = l1;
    }

    float m0 = -1e30f, m1 = -1e30f, l0s = 0.f, l1s = 0.f;
    float acc[16][4];
#pragma unroll
    for (int t = 0; t < 16; ++t)
#pragma unroll
        for (int e = 0; e < 4; ++e) acc[t][e] = 0.f;

    const int qr0 = ib * 128 + warp * 16 + r;   // row of c0,c1
    const int qr1 = qr0 + 8;
    const int jmax = 2 * ib + 1;

    for (int j = 0; j <= jmax; ++j) {
        __syncthreads();   // prior tile's MMA reads done
        // ---- load + convert K and V tiles (64 x 128 each) ----
        for (int i = tid; i < 64 * 32; i += 256) {
            int row = i >> 5;
            int hd4 = (i & 31) * 4;
            int w = row * 68 + (hd4 >> 1);
            float4 f = *(const float4*)&Kg[(size_t)(j * 64 + row) * KD_ + hd4];
            unsigned h0 = pk2(f.x, f.y), h1 = pk2(f.z, f.w);
            KHI[w] = h0; KHI[w + 1] = h1;
            KLO[w]     = pk2(f.x - blo(h0), f.y - bhi(h0));
            KLO[w + 1] = pk2(f.z - blo(h1), f.w - bhi(h1));
            float4 g = *(const float4*)&Vg[(size_t)(j * 64 + row) * KD_ + hd4];
            unsigned v0 = pk2(g.x, g.y), v1 = pk2(g.z, g.w);
            VHI[w] = v0; VHI[w + 1] = v1;
            VLO[w]     = pk2(g.x - blo(v0), g.y - bhi(v0));
            VLO[w + 1] = pk2(g.z - blo(v1), g.w - bhi(v1));
        }
        __syncthreads();

        // ---- QK^T: s[8 n-tiles][4] over kv cols of this tile ----
        float s[8][4];
#pragma unroll
        for (int bn = 0; bn < 8; ++bn)
#pragma unroll
            for (int e = 0; e < 4; ++e) s[bn][e] = 0.f;

#pragma unroll
        for (int kk = 0; kk < 8; ++kk) {
            int a0i = (warp * 16 + r) * 68 + kk * 8 + c;
            int a1i = a0i + 8 * 68;
            unsigned ah0 = QHI[a0i], ah1 = QHI[a1i], ah2 = QHI[a0i + 4], ah3 = QHI[a1i + 4];
            unsigned al0 = QLO[a0i], al1 = QLO[a1i], al2 = QLO[a0i + 4], al3 = QLO[a1i + 4];
#pragma unroll
            for (int bn = 0; bn < 8; ++bn) {
                int bi = (bn * 8 + r) * 68 + kk * 8 + c;
                unsigned kb0 = KHI[bi], kb1 = KHI[bi + 4];
                unsigned kl0 = KLO[bi], kl1 = KLO[bi + 4];
                MMA_BF16(s[bn], ah0, ah1, ah2, ah3, kb0, kb1);
                MMA_BF16(s[bn], ah0, ah1, ah2, ah3, kl0, kl1);
                MMA_BF16(s[bn], al0, al1, al2, al3, kb0, kb1);
            }
        }

        // ---- scale, mask, online softmax ----
        const bool need_mask = (j >= 2 * ib);
        float vmax0 = -1e30f, vmax1 = -1e30f;
#pragma unroll
        for (int bn = 0; bn < 8; ++bn) {
#pragma unroll
            for (int e = 0; e < 2; ++e) {
                int col = j * 64 + bn * 8 + 2 * c + e;
                float v0 = s[bn][e] * scale;
                if (need_mask && col > qr0) v0 = -1e30f;
                s[bn][e] = v0;
                vmax0 = fmaxf(vmax0, v0);
                float v1 = s[bn][2 + e] * scale;
                if (need_mask && col > qr1) v1 = -1e30f;
                s[bn][2 + e] = v1;
                vmax1 = fmaxf(vmax1, v1);
            }
        }
        vmax0 = fmaxf(vmax0, __shfl_xor_sync(0xffffffffu, vmax0, 1));
        vmax0 = fmaxf(vmax0, __shfl_xor_sync(0xffffffffu, vmax0, 2));
        vmax1 = fmaxf(vmax1, __shfl_xor_sync(0xffffffffu, vmax1, 1));
        vmax1 = fmaxf(vmax1, __shfl_xor_sync(0xffffffffu, vmax1, 2));

        float mn0 = fmaxf(m0, vmax0), mn1 = fmaxf(m1, vmax1);
        float alpha0 = __expf(m0 - mn0), alpha1 = __expf(m1 - mn1);
        m0 = mn0; m1 = mn1;

        float rs0 = 0.f, rs1 = 0.f;
#pragma unroll
        for (int bn = 0; bn < 8; ++bn) {
#pragma unroll
            for (int e = 0; e < 2; ++e) {
                float p0 = __expf(s[bn][e] - mn0);
                s[bn][e] = p0; rs0 += p0;
                float p1 = __expf(s[bn][2 + e] - mn1);
                s[bn][2 + e] = p1; rs1 += p1;
            }
        }
        rs0 += __shfl_xor_sync(0xffffffffu, rs0, 1);
        rs0 += __shfl_xor_sync(0xffffffffu, rs0, 2);
        rs1 += __shfl_xor_sync(0xffffffffu, rs1, 1);
        rs1 += __shfl_xor_sync(0xffffffffu, rs1, 2);
        l0s = l0s * alpha0 + rs0;
        l1s = l1s * alpha1 + rs1;

#pragma unroll
        for (int t = 0; t < 16; ++t) {
            acc[t][0] *= alpha0; acc[t][1] *= alpha0;
            acc[t][2] *= alpha1; acc[t][3] *= alpha1;
        }

        // ---- PV: acc += P * V  (P in regs from s; V via ldmatrix.trans) ----
#pragma unroll
        for (int kk = 0; kk < 4; ++kk) {
            // P A-fragments (hi/lo split), k window = kv cols 16kk..16kk+15
            unsigned ph0 = pk2(s[2 * kk][0], s[2 * kk][1]);
            unsigned ph1 = pk2(s[2 * kk][2], s[2 * kk][3]);
            unsigned ph2 = pk2(s[2 * kk + 1][0], s[2 * kk + 1][1]);
            unsigned ph3 = pk2(s[2 * kk + 1][2], s[2 * kk + 1][3]);
            unsigned pl0 = pk2(s[2 * kk][0] - blo(ph0), s[2 * kk][1] - bhi(ph0));
            unsigned pl1 = pk2(s[2 * kk][2] - blo(ph1), s[2 * kk][3] - bhi(ph1));
            unsigned pl2 = pk2(s[2 * kk + 1][0] - blo(ph2), s[2 * kk + 1][1] - bhi(ph2));
            unsigned pl3 = pk2(s[2 * kk + 1][2] - blo(ph3), s[2 * kk + 1][3] - bhi(ph3));

            int sel = lane >> 3;        // 0..3: which 8x8 matrix
            int lrow = lane & 7;
            int vrow = kk * 16 + (sel & 1) * 8 + lrow;
            int coff = (sel >> 1) * 8;  // +0 or +8 bf16 cols

#pragma unroll
            for (int t = 0; t < 16; t += 2) {
                unsigned addr_h = smb + VHI_OFF * 4u + (unsigned)(vrow * 272 + (t * 8 + coff) * 2);
                unsigned addr_l = smb + VLO_OFF * 4u + (unsigned)(vrow * 272 + (t * 8 + coff) * 2);
                unsigned vh0, vh1, vh2, vh3, vl0, vl1, vl2, vl3;
                asm volatile("ldmatrix.sync.aligned.m8n8.x4.trans.shared.b16 {%0,%1,%2,%3}, [%4];"
                             : "=r"(vh0), "=r"(vh1), "=r"(vh2), "=r"(vh3) : "r"(addr_h));
                asm volatile("ldmatrix.sync.aligned.m8n8.x4.trans.shared.b16 {%0,%1,%2,%3}, [%4];"
                             : "=r"(vl0), "=r"(vl1), "=r"(vl2), "=r"(vl3) : "r"(addr_l));
                MMA_BF16(acc[t],     ph0, ph1, ph2, ph3, vh0, vh1);
                MMA_BF16(acc[t],     ph0, ph1, ph2, ph3, vl0, vl1);
                MMA_BF16(acc[t],     pl0, pl1, pl2, pl3, vh0, vh1);
                MMA_BF16(acc[t + 1], ph0, ph1, ph2, ph3, vh2, vh3);
                MMA_BF16(acc[t + 1], ph0, ph1, ph2, ph3, vl2, vl3);
                MMA_BF16(acc[t + 1], pl0, pl1, pl2, pl3, vh2, vh3);
            }
        }
    }

    // ---- epilogue ----
    float inv0 = 1.f / l0s, inv1 = 1.f / l1s;
#pragma unroll
    for (int t = 0; t < 16; ++t) {
        int col = t * 8 + 2 * c;
        float* d0 = O + (size_t)(b * S_ + qr0) * QD_ + (size_t)h * HD_ + col;
        float* d1 = O + (size_t)(b * S_ + qr1) * QD_ + (size_t)h * HD_ + col;
        *(float2*)d0 = make_float2(acc[t][0] * inv0, acc[t][1] * inv0);
        *(float2*)d1 = make_float2(acc[t][2] * inv1, acc[t][3] * inv1);
    }
}

// ---------------------------------------------------------------------------
extern "C" void kernel_launch(void* const* d_in, const int* in_sizes, int n_in,
                              void* d_out, int out_size)
{
    const float* x     = (const float*)d_in[0];
    const float* freqs = (const float*)d_in[1];
    const float* wq    = (const float*)d_in[2];
    const float* wk    = (const float*)d_in[3];
    const float* wv    = (const float*)d_in[4];
    const float* wo    = (const float*)d_in[5];
    float* out = (float*)d_out;

    float *q, *k, *v, *attn;
    cudaGetSymbolAddress((void**)&q,    g_q);
    cudaGetSymbolAddress((void**)&k,    g_k);
    cudaGetSymbolAddress((void**)&v,    g_v);
    cudaGetSymbolAddress((void**)&attn, g_attn);

    static int attr_set = 0;
    const int gemm_smem  = 65536;
    const int flash_smem = FLASH_SMEM_WORDS * 4;  // 139264
    if (!attr_set) {
        cudaFuncSetAttribute(gemm_tf32x3_kernel,
                             cudaFuncAttributeMaxDynamicSharedMemorySize, gemm_smem);
        cudaFuncSetAttribute(flash_bf16_kernel,
                             cudaFuncAttributeMaxDynamicSharedMemorySize, flash_smem);
        attr_set = 1;
    }

    // QKV projections (3xtf32 tensor-core)
    gemm_tf32x3_kernel<<<dim3(QD_ / 128, M_ / 128), 256, gemm_smem>>>(x, wq, q, QD_, DIM_);
    gemm_tf32x3_kernel<<<dim3(KD_ / 128, M_ / 128), 256, gemm_smem>>>(x, wk, k, KD_, DIM_);
    gemm_tf32x3_kernel<<<dim3(KD_ / 128, M_ / 128), 256, gemm_smem>>>(x, wv, v, KD_, DIM_);

    // RoPE
    {
        int tq = B_ * S_ * H_ * (HD_ / 2);
        int tk = B_ * S_ * KVH_ * (HD_ / 2);
        rope_kernel<<<(tq + 255) / 256, 256>>>(q, freqs, H_);
        rope_kernel<<<(tk + 255) / 256, 256>>>(k, freqs, KVH_);
    }

    // Flash attention (bf16x3 tensor-core)
    flash_bf16_kernel<<<dim3(B_ * H_, S_ / 128), 256, flash_smem>>>(q, k, v, attn);

    // Output projection (3xtf32 tensor-core)
    gemm_tf32x3_kernel<<<dim3(DIM_ / 128, M_ / 128), 256, gemm_smem>>>(attn, wo, out, DIM_, QD_);
}

// round 6
// speedup vs baseline: 3.2386x; 1.4286x over previous
#include <cuda_runtime.h>
#include <math.h>
#include <float.h>

#define B_    2
#define S_    2048
#define DIM_  2048
#define H_    16
#define KVH_  4
#define HD_   128
#define G_    4
#define M_    (B_*S_)          // 4096 rows total
#define QD_   (H_*HD_)         // 2048
#define KD_   (KVH_*HD_)       // 512

// Scratch (device globals -- no allocation)
__device__ float g_q[(size_t)M_*QD_];     // [b,s,h,hd]
__device__ float g_k[(size_t)M_*KD_];     // [b,s,kvh,hd]
__device__ float g_v[(size_t)M_*KD_];
__device__ float g_attn[(size_t)M_*QD_];  // [b,s,h,hd]

// ---------------------------------------------------------------------------
// helpers
// ---------------------------------------------------------------------------
// pack two floats into bf16x2: low half = lo_elem, high half = hi_elem
__device__ __forceinline__ unsigned pk2(float lo_elem, float hi_elem) {
    unsigned d;
    asm("cvt.rn.bf16x2.f32 %0, %1, %2;" : "=r"(d) : "f"(hi_elem), "f"(lo_elem));
    return d;
}
__device__ __forceinline__ float blo(unsigned u) { return __uint_as_float(u << 16); }
__device__ __forceinline__ float bhi(unsigned u) { return __uint_as_float(u & 0xffff0000u); }

#define MMA_BF16(d, a0, a1, a2, a3, b0, b1) \
    asm volatile("mma.sync.aligned.m16n8k16.row.col.f32.bf16.bf16.f32 " \
                 "{%0,%1,%2,%3},{%4,%5,%6,%7},{%8,%9},{%0,%1,%2,%3};" \
                 : "+f"(d[0]), "+f"(d[1]), "+f"(d[2]), "+f"(d[3]) \
                 : "r"(a0), "r"(a1), "r"(a2), "r"(a3), "r"(b0), "r"(b1))

// ---------------------------------------------------------------------------
// bf16x3 tensor-core GEMM: C[M,N] = A[M,K] * W[N,K]^T  (fp32-accurate)
// 128x128x32 block tile, 256 threads (8 warps 2x4), warp tile 64x32.
// Operands split hi/lo bf16 ONCE at smem-fill; D += Ah*Bh + Ah*Bl + Al*Bh.
// Register-prefetch double buffer. Optional fused RoPE on the output pairs.
// smem words (u32 = bf16x2), row stride 20 (16 data + 4 pad):
//   per stage: AHI[128][20] ALO BHI BLO  = 10240 words; 2 stages = 80KB.
// ---------------------------------------------------------------------------
#define RS_   20
#define STG_  10240
#define AHI_O 0
#define ALO_O 2560
#define BHI_O 5120
#define BLO_O 7680

__global__ __launch_bounds__(256, 2) void gemm_bf16x3_kernel(
    const float* __restrict__ A, const float* __restrict__ W,
    float* __restrict__ C, int Nn, int Kn,
    int do_rope, const float* __restrict__ freqs)
{
    extern __shared__ unsigned smw[];

    const int tid  = threadIdx.x;
    const int lane = tid & 31;
    const int warp = tid >> 5;
    const int warpM = (warp >> 2) * 64;   // 0 or 64
    const int warpN = (warp & 3) * 32;    // 0,32,64,96
    const int r = lane >> 2;              // 0..7
    const int c = lane & 3;               // 0..3
    const int m0 = blockIdx.y * 128;
    const int n0 = blockIdx.x * 128;

    const int lrow = tid >> 3;            // 0..31
    const int lg   = tid & 7;             // k float4 group

    float acc[4][4][4];
#pragma unroll
    for (int i = 0; i < 4; ++i)
#pragma unroll
        for (int j = 0; j < 4; ++j)
#pragma unroll
            for (int t = 0; t < 4; ++t) acc[i][j][t] = 0.f;

    const int NT = Kn >> 5;

    float4 pa[4], pb[4];

    auto issue_loads = [&](int it) {
        size_t k0 = (size_t)it * 32 + lg * 4;
#pragma unroll
        for (int i = 0; i < 4; ++i) {
            int rr = lrow + i * 32;
            pa[i] = *(const float4*)&A[(size_t)(m0 + rr) * Kn + k0];
            pb[i] = *(const float4*)&W[(size_t)(n0 + rr) * Kn + k0];
        }
    };

    auto store_tile = [&](int p) {
        unsigned* base = smw + p * STG_;
#pragma unroll
        for (int i = 0; i < 4; ++i) {
            int rr = lrow + i * 32;
            int w = rr * RS_ + lg * 2;
            unsigned h0 = pk2(pa[i].x, pa[i].y), h1 = pk2(pa[i].z, pa[i].w);
            *(uint2*)&base[AHI_O + w] = make_uint2(h0, h1);
            *(uint2*)&base[ALO_O + w] = make_uint2(
                pk2(pa[i].x - blo(h0), pa[i].y - bhi(h0)),
                pk2(pa[i].z - blo(h1), pa[i].w - bhi(h1)));
            unsigned g0 = pk2(pb[i].x, pb[i].y), g1 = pk2(pb[i].z, pb[i].w);
            *(uint2*)&base[BHI_O + w] = make_uint2(g0, g1);
            *(uint2*)&base[BLO_O + w] = make_uint2(
                pk2(pb[i].x - blo(g0), pb[i].y - bhi(g0)),
                pk2(pb[i].z - blo(g1), pb[i].w - bhi(g1)));
        }
    };

    issue_loads(0);
    store_tile(0);
    __syncthreads();

    for (int it = 0; it < NT; ++it) {
        if (it + 1 < NT) issue_loads(it + 1);

        const unsigned* st = smw + (it & 1) * STG_;
#pragma unroll
        for (int kk = 0; kk < 2; ++kk) {
            unsigned bh_[4][2], bl_[4][2];
#pragma unroll
            for (int bn = 0; bn < 4; ++bn) {
                int bw = (warpN + bn * 8 + r) * RS_ + kk * 8 + c;
                bh_[bn][0] = st[BHI_O + bw]; bh_[bn][1] = st[BHI_O + bw + 4];
                bl_[bn][0] = st[BLO_O + bw]; bl_[bn][1] = st[BLO_O + bw + 4];
            }
#pragma unroll
            for (int am = 0; am < 4; ++am) {
                int aw = (warpM + am * 16 + r) * RS_ + kk * 8 + c;
                unsigned ah0 = st[AHI_O + aw];
                unsigned ah1 = st[AHI_O + aw + 8 * RS_];
                unsigned ah2 = st[AHI_O + aw + 4];
                unsigned ah3 = st[AHI_O + aw + 8 * RS_ + 4];
                unsigned al0 = st[ALO_O + aw];
                unsigned al1 = st[ALO_O + aw + 8 * RS_];
                unsigned al2 = st[ALO_O + aw + 4];
                unsigned al3 = st[ALO_O + aw + 8 * RS_ + 4];
#pragma unroll
                for (int bn = 0; bn < 4; ++bn) {
                    MMA_BF16(acc[am][bn], ah0, ah1, ah2, ah3, bh_[bn][0], bh_[bn][1]);
                    MMA_BF16(acc[am][bn], ah0, ah1, ah2, ah3, bl_[bn][0], bl_[bn][1]);
                    MMA_BF16(acc[am][bn], al0, al1, al2, al3, bh_[bn][0], bh_[bn][1]);
                }
            }
        }

        if (it + 1 < NT) store_tile((it + 1) & 1);
        __syncthreads();
    }

    // epilogue (optionally fused RoPE: output pair (n1, n1+1) is a rope pair)
#pragma unroll
    for (int am = 0; am < 4; ++am) {
        int m1 = m0 + warpM + am * 16 + r;
#pragma unroll
        for (int bn = 0; bn < 4; ++bn) {
            int n1 = n0 + warpN + bn * 8 + 2 * c;
            float2 v0 = make_float2(acc[am][bn][0], acc[am][bn][1]);
            float2 v1 = make_float2(acc[am][bn][2], acc[am][bn][3]);
            if (do_rope) {
                int j = (n1 & (HD_ - 1)) >> 1;
                int s0 = m1 & (S_ - 1);
                int s1 = (m1 + 8) & (S_ - 1);
                float2 cs0 = *(const float2*)&freqs[((size_t)s0 * 64 + j) * 2];
                float2 cs1 = *(const float2*)&freqs[((size_t)s1 * 64 + j) * 2];
                v0 = make_float2(v0.x * cs0.x - v0.y * cs0.y,
                                 v0.x * cs0.y + v0.y * cs0.x);
                v1 = make_float2(v1.x * cs1.x - v1.y * cs1.y,
                                 v1.x * cs1.y + v1.y * cs1.x);
            }
            *(float2*)&C[(size_t)m1 * Nn + n1] = v0;
            *(float2*)&C[(size_t)(m1 + 8) * Nn + n1] = v1;
        }
    }
}

// ---------------------------------------------------------------------------
// Flash attention, bf16x3 tensor-core version (causal, GQA).
// Block: 256 thr (8 warps). q-tile 128 rows, kv-tile 64. Warp w owns q rows
// [w*16, w*16+16). Q/K/V split hi/lo bf16 in smem; P kept in registers.
// ---------------------------------------------------------------------------
#define QHI_OFF 0
#define QLO_OFF 8704
#define KHI_OFF 17408
#define KLO_OFF 21760
#define VHI_OFF 26112
#define VLO_OFF 30464
#define FLASH_SMEM_WORDS 34816

__global__ __launch_bounds__(256, 1) void flash_bf16_kernel(
    const float* __restrict__ Q, const float* __restrict__ K,
    const float* __restrict__ V, float* __restrict__ O)
{
    extern __shared__ unsigned smw[];
    unsigned* QHI = smw + QHI_OFF;
    unsigned* QLO = smw + QLO_OFF;
    unsigned* KHI = smw + KHI_OFF;
    unsigned* KLO = smw + KLO_OFF;
    unsigned* VHI = smw + VHI_OFF;
    unsigned* VLO = smw + VLO_OFF;
    const unsigned smb = (unsigned)__cvta_generic_to_shared(smw);

    const int bh = blockIdx.x;                 // 0..31
    const int ib = (int)gridDim.y - 1 - (int)blockIdx.y;  // heavy tiles first
    const int b  = bh / H_;
    const int h  = bh % H_;
    const int kv = h / G_;

    const float* Qg = Q + (size_t)b * S_ * QD_ + (size_t)h * HD_;
    const float* Kg = K + (size_t)b * S_ * KD_ + (size_t)kv * HD_;
    const float* Vg = V + (size_t)b * S_ * KD_ + (size_t)kv * HD_;

    const int tid  = threadIdx.x;
    const int lane = tid & 31;
    const int warp = tid >> 5;
    const int r = lane >> 2;      // 0..7
    const int c = lane & 3;       // 0..3
    const float scale = 0.08838834764831845f;

    // ---- load + convert Q tile (128 x 128) once ----
    for (int i = tid; i < 128 * 32; i += 256) {
        int row = i >> 5;
        int hd4 = (i & 31) * 4;
        float4 f = *(const float4*)&Qg[(size_t)(ib * 128 + row) * QD_ + hd4];
        unsigned h0 = pk2(f.x, f.y), h1 = pk2(f.z, f.w);
        unsigned l0 = pk2(f.x - blo(h0), f.y - bhi(h0));
        unsigned l1 = pk2(f.z - blo(h1), f.w - bhi(h1));
        int w = row * 68 + (hd4 >> 1);
        QHI[w] = h0; QHI[w + 1] = h1;
        QLO[w] = l0; QLO[w + 1] = l1;
    }

    float m0 = -1e30f, m1 = -1e30f, l0s = 0.f, l1s = 0.f;
    float acc[16][4];
#pragma unroll
    for (int t = 0; t < 16; ++t)
#pragma unroll
        for (int e = 0; e < 4; ++e) acc[t][e] = 0.f;

    const int qr0 = ib * 128 + warp * 16 + r;   // row of c0,c1
    const int qr1 = qr0 + 8;
    const int jmax = 2 * ib + 1;

    for (int j = 0; j <= jmax; ++j) {
        __syncthreads();   // prior tile's MMA reads done
        // ---- load + convert K and V tiles (64 x 128 each) ----
        for (int i = tid; i < 64 * 32; i += 256) {
            int row = i >> 5;
            int hd4 = (i & 31) * 4;
            int w = row * 68 + (hd4 >> 1);
            float4 f = *(const float4*)&Kg[(size_t)(j * 64 + row) * KD_ + hd4];
            unsigned h0 = pk2(f.x, f.y), h1 = pk2(f.z, f.w);
            KHI[w] = h0; KHI[w + 1] = h1;
            KLO[w]     = pk2(f.x - blo(h0), f.y - bhi(h0));
            KLO[w + 1] = pk2(f.z - blo(h1), f.w - bhi(h1));
            float4 g = *(const float4*)&Vg[(size_t)(j * 64 + row) * KD_ + hd4];
            unsigned v0 = pk2(g.x, g.y), v1 = pk2(g.z, g.w);
            VHI[w] = v0; VHI[w + 1] = v1;
            VLO[w]     = pk2(g.x - blo(v0), g.y - bhi(v0));
            VLO[w + 1] = pk2(g.z - blo(v1), g.w - bhi(v1));
        }
        __syncthreads();

        // ---- QK^T ----
        float s[8][4];
#pragma unroll
        for (int bn = 0; bn < 8; ++bn)
#pragma unroll
            for (int e = 0; e < 4; ++e) s[bn][e] = 0.f;

#pragma unroll
        for (int kk = 0; kk < 8; ++kk) {
            int a0i = (warp * 16 + r) * 68 + kk * 8 + c;
            int a1i = a0i + 8 * 68;
            unsigned ah0 = QHI[a0i], ah1 = QHI[a1i], ah2 = QHI[a0i + 4], ah3 = QHI[a1i + 4];
            unsigned al0 = QLO[a0i], al1 = QLO[a1i], al2 = QLO[a0i + 4], al3 = QLO[a1i + 4];
#pragma unroll
            for (int bn = 0; bn < 8; ++bn) {
                int bi = (bn * 8 + r) * 68 + kk * 8 + c;
                unsigned kb0 = KHI[bi], kb1 = KHI[bi + 4];
                unsigned kl0 = KLO[bi], kl1 = KLO[bi + 4];
                MMA_BF16(s[bn], ah0, ah1, ah2, ah3, kb0, kb1);
                MMA_BF16(s[bn], ah0, ah1, ah2, ah3, kl0, kl1);
                MMA_BF16(s[bn], al0, al1, al2, al3, kb0, kb1);
            }
        }

        // ---- scale, mask, online softmax ----
        const bool need_mask = (j >= 2 * ib);
        float vmax0 = -1e30f, vmax1 = -1e30f;
#pragma unroll
        for (int bn = 0; bn < 8; ++bn) {
#pragma unroll
            for (int e = 0; e < 2; ++e) {
                int col = j * 64 + bn * 8 + 2 * c + e;
                float v0 = s[bn][e] * scale;
                if (need_mask && col > qr0) v0 = -1e30f;
                s[bn][e] = v0;
                vmax0 = fmaxf(vmax0, v0);
                float v1 = s[bn][2 + e] * scale;
                if (need_mask && col > qr1) v1 = -1e30f;
                s[bn][2 + e] = v1;
                vmax1 = fmaxf(vmax1, v1);
            }
        }
        vmax0 = fmaxf(vmax0, __shfl_xor_sync(0xffffffffu, vmax0, 1));
        vmax0 = fmaxf(vmax0, __shfl_xor_sync(0xffffffffu, vmax0, 2));
        vmax1 = fmaxf(vmax1, __shfl_xor_sync(0xffffffffu, vmax1, 1));
        vmax1 = fmaxf(vmax1, __shfl_xor_sync(0xffffffffu, vmax1, 2));

        float mn0 = fmaxf(m0, vmax0), mn1 = fmaxf(m1, vmax1);
        float alpha0 = __expf(m0 - mn0), alpha1 = __expf(m1 - mn1);
        m0 = mn0; m1 = mn1;

        float rs0 = 0.f, rs1 = 0.f;
#pragma unroll
        for (int bn = 0; bn < 8; ++bn) {
#pragma unroll
            for (int e = 0; e < 2; ++e) {
                float p0 = __expf(s[bn][e] - mn0);
                s[bn][e] = p0; rs0 += p0;
                float p1 = __expf(s[bn][2 + e] - mn1);
                s[bn][2 + e] = p1; rs1 += p1;
            }
        }
        rs0 += __shfl_xor_sync(0xffffffffu, rs0, 1);
        rs0 += __shfl_xor_sync(0xffffffffu, rs0, 2);
        rs1 += __shfl_xor_sync(0xffffffffu, rs1, 1);
        rs1 += __shfl_xor_sync(0xffffffffu, rs1, 2);
        l0s = l0s * alpha0 + rs0;
        l1s = l1s * alpha1 + rs1;

#pragma unroll
        for (int t = 0; t < 16; ++t) {
            acc[t][0] *= alpha0; acc[t][1] *= alpha0;
            acc[t][2] *= alpha1; acc[t][3] *= alpha1;
        }

        // ---- PV ----
#pragma unroll
        for (int kk = 0; kk < 4; ++kk) {
            unsigned ph0 = pk2(s[2 * kk][0], s[2 * kk][1]);
            unsigned ph1 = pk2(s[2 * kk][2], s[2 * kk][3]);
            unsigned ph2 = pk2(s[2 * kk + 1][0], s[2 * kk + 1][1]);
            unsigned ph3 = pk2(s[2 * kk + 1][2], s[2 * kk + 1][3]);
            unsigned pl0 = pk2(s[2 * kk][0] - blo(ph0), s[2 * kk][1] - bhi(ph0));
            unsigned pl1 = pk2(s[2 * kk][2] - blo(ph1), s[2 * kk][3] - bhi(ph1));
            unsigned pl2 = pk2(s[2 * kk + 1][0] - blo(ph2), s[2 * kk + 1][1] - bhi(ph2));
            unsigned pl3 = pk2(s[2 * kk + 1][2] - blo(ph3), s[2 * kk + 1][3] - bhi(ph3));

            int sel = lane >> 3;
            int lrow = lane & 7;
            int vrow = kk * 16 + (sel & 1) * 8 + lrow;
            int coff = (sel >> 1) * 8;

#pragma unroll
            for (int t = 0; t < 16; t += 2) {
                unsigned addr_h = smb + VHI_OFF * 4u + (unsigned)(vrow * 272 + (t * 8 + coff) * 2);
                unsigned addr_l = smb + VLO_OFF * 4u + (unsigned)(vrow * 272 + (t * 8 + coff) * 2);
                unsigned vh0, vh1, vh2, vh3, vl0, vl1, vl2, vl3;
                asm volatile("ldmatrix.sync.aligned.m8n8.x4.trans.shared.b16 {%0,%1,%2,%3}, [%4];"
                             : "=r"(vh0), "=r"(vh1), "=r"(vh2), "=r"(vh3) : "r"(addr_h));
                asm volatile("ldmatrix.sync.aligned.m8n8.x4.trans.shared.b16 {%0,%1,%2,%3}, [%4];"
                             : "=r"(vl0), "=r"(vl1), "=r"(vl2), "=r"(vl3) : "r"(addr_l));
                MMA_BF16(acc[t],     ph0, ph1, ph2, ph3, vh0, vh1);
                MMA_BF16(acc[t],     ph0, ph1, ph2, ph3, vl0, vl1);
                MMA_BF16(acc[t],     pl0, pl1, pl2, pl3, vh0, vh1);
                MMA_BF16(acc[t + 1], ph0, ph1, ph2, ph3, vh2, vh3);
                MMA_BF16(acc[t + 1], ph0, ph1, ph2, ph3, vl2, vl3);
                MMA_BF16(acc[t + 1], pl0, pl1, pl2, pl3, vh2, vh3);
            }
        }
    }

    // ---- epilogue ----
    float inv0 = 1.f / l0s, inv1 = 1.f / l1s;
#pragma unroll
    for (int t = 0; t < 16; ++t) {
        int col = t * 8 + 2 * c;
        float* d0 = O + (size_t)(b * S_ + qr0) * QD_ + (size_t)h * HD_ + col;
        float* d1 = O + (size_t)(b * S_ + qr1) * QD_ + (size_t)h * HD_ + col;
        *(float2*)d0 = make_float2(acc[t][0] * inv0, acc[t][1] * inv0);
        *(float2*)d1 = make_float2(acc[t][2] * inv1, acc[t][3] * inv1);
    }
}

// ---------------------------------------------------------------------------
extern "C" void kernel_launch(void* const* d_in, const int* in_sizes, int n_in,
                              void* d_out, int out_size)
{
    const float* x     = (const float*)d_in[0];
    const float* freqs = (const float*)d_in[1];
    const float* wq    = (const float*)d_in[2];
    const float* wk    = (const float*)d_in[3];
    const float* wv    = (const float*)d_in[4];
    const float* wo    = (const float*)d_in[5];
    float* out = (float*)d_out;

    float *q, *k, *v, *attn;
    cudaGetSymbolAddress((void**)&q,    g_q);
    cudaGetSymbolAddress((void**)&k,    g_k);
    cudaGetSymbolAddress((void**)&v,    g_v);
    cudaGetSymbolAddress((void**)&attn, g_attn);

    static int attr_set = 0;
    const int gemm_smem  = 2 * STG_ * 4;          // 81920
    const int flash_smem = FLASH_SMEM_WORDS * 4;  // 139264
    if (!attr_set) {
        cudaFuncSetAttribute(gemm_bf16x3_kernel,
                             cudaFuncAttributeMaxDynamicSharedMemorySize, gemm_smem);
        cudaFuncSetAttribute(flash_bf16_kernel,
                             cudaFuncAttributeMaxDynamicSharedMemorySize, flash_smem);
        attr_set = 1;
    }

    // QKV projections (bf16x3 tensor-core, RoPE fused for Q and K)
    gemm_bf16x3_kernel<<<dim3(QD_ / 128, M_ / 128), 256, gemm_smem>>>(x, wq, q, QD_, DIM_, 1, freqs);
    gemm_bf16x3_kernel<<<dim3(KD_ / 128, M_ / 128), 256, gemm_smem>>>(x, wk, k, KD_, DIM_, 1, freqs);
    gemm_bf16x3_kernel<<<dim3(KD_ / 128, M_ / 128), 256, gemm_smem>>>(x, wv, v, KD_, DIM_, 0, freqs);

    // Flash attention (bf16x3 tensor-core)
    flash_bf16_kernel<<<dim3(B_ * H_, S_ / 128), 256, flash_smem>>>(q, k, v, attn);

    // Output projection (bf16x3 tensor-core)
    gemm_bf16x3_kernel<<<dim3(DIM_ / 128, M_ / 128), 256, gemm_smem>>>(attn, wo, out, DIM_, QD_, 0, freqs);
}